// round 15
// baseline (speedup 1.0000x reference)
#include <cuda_runtime.h>
#include <cuda_fp16.h>
#include <cstdint>

#define N_NODES 100000
#define HEADS 8
#define F_IN 128
#define F1 128          // HEADS * 16
#define F2 64           // HEADS * 8
#define NEG_SLOPE 0.2f
#define MAX_E 1800000

// ---------------- static device scratch (no allocations allowed) ----------------
__device__ float g_h1[(size_t)N_NODES * F1 / 2];  // layer-1 projected features (fp16, reinterpreted)
__device__ float g_out1[(size_t)N_NODES * F1];    // layer-1 output (normalized+bias+relu)
__device__ float g_s_src1[(size_t)N_NODES * HEADS];
__device__ float g_s_dst1[(size_t)N_NODES * HEADS];
__device__ float g_h2[(size_t)N_NODES * F2];
__device__ float g_s_src2[(size_t)N_NODES * HEADS];
__device__ float g_s_dst2[(size_t)N_NODES * HEADS];
__device__ int   g_idx64;                          // 1 if edge_index is int64, 0 if int32

// transposed weights: WT[col][k]
__device__ float g_WT1[F_IN * F1];
__device__ float g_WT2[F_IN * F2];

// CSR-by-destination (rebuilt every launch; graph inputs are constant per call)
__device__ int g_deg[N_NODES];
__device__ int g_off[N_NODES + 1];
__device__ int g_cur[N_NODES];
__device__ int g_src_sorted[MAX_E];

// ---------------- helpers ----------------
__device__ __forceinline__ float lrelu(float z) {
    return z > 0.f ? z : NEG_SLOPE * z;
}

// packed dual-fp32 FMA (sm_100+): d.lo += a.lo*b.lo ; d.hi += a.hi*b.hi
__device__ __forceinline__ void fma2(unsigned long long& d,
                                     unsigned long long a,
                                     unsigned long long b) {
    asm("fma.rn.f32x2 %0, %1, %2, %0;" : "+l"(d) : "l"(a), "l"(b));
}

__device__ __forceinline__ float pair_sum(unsigned long long v) {
    float lo = __uint_as_float((unsigned)(v & 0xffffffffULL));
    float hi = __uint_as_float((unsigned)(v >> 32));
    return lo + hi;
}

// load one 4-col slice of an h row, fp16 or fp32 backing
template<bool HALF_IN>
__device__ __forceinline__ float4 load_h4(const void* h, size_t row, int F_OUT, int sub) {
    if (HALF_IN) {
        uint2 r = *(const uint2*)((const __half*)h + row * F_OUT + sub * 4);
        __half2* ph = (__half2*)&r;
        float2 f01 = __half22float2(ph[0]);
        float2 f23 = __half22float2(ph[1]);
        return make_float4(f01.x, f01.y, f23.x, f23.y);
    } else {
        return *(const float4*)((const float*)h + row * F_OUT + sub * 4);
    }
}

// ---------------- dtype detect + weight transpose (merged) ----------------
__global__ __launch_bounds__(256)
void prep_kernel(const long long* __restrict__ e,
                 const float* __restrict__ W1, const float* __restrict__ W2) {
    if (blockIdx.x == 0) {
        long long v = e[threadIdx.x];
        int bad = (v < 0 || v >= (long long)N_NODES);
        int any = __syncthreads_or(bad);
        if (threadIdx.x == 0) g_idx64 = !any;
        return;
    }
    int t = (blockIdx.x - 1) * 256 + threadIdx.x;
    if (t < F_IN * F1) {
        int c = t / F_IN, k = t % F_IN;
        g_WT1[t] = W1[k * F1 + c];
    } else {
        int u = t - F_IN * F1;
        if (u < F_IN * F2) {
            int c = u / F_IN, k = u % F_IN;
            g_WT2[u] = W2[k * F2 + c];
        }
    }
}

// ---------------- CSR build: histogram -> single-block scan -> scatter ----------------
__global__ __launch_bounds__(256)
void hist_kernel(const void* __restrict__ eptr, int E) {
    int i = blockIdx.x * blockDim.x + threadIdx.x;
    if (i >= E) return;
    int dst = g_idx64 ? (int)((const long long*)eptr)[(size_t)E + i]
                      : ((const int*)eptr)[E + i];
    atomicAdd(&g_deg[dst], 1);
}

// one block, 1024 threads: each thread owns a contiguous chunk of ~98 nodes.
__global__ __launch_bounds__(1024)
void scan_all_kernel(int E) {
    __shared__ int wsum[32];
    const int T = 1024;
    int tid = threadIdx.x;
    int chunk = (N_NODES + T - 1) / T;
    int start = tid * chunk;
    int end = start + chunk; if (end > N_NODES) end = N_NODES;
    int sum = 0;
    for (int i = start; i < end; i++) sum += g_deg[i];

    int lane = tid & 31, wid = tid >> 5;
    int s = sum;
    #pragma unroll
    for (int off = 1; off < 32; off <<= 1) {
        int t = __shfl_up_sync(0xffffffffu, s, off);
        if (lane >= off) s += t;
    }
    if (lane == 31) wsum[wid] = s;
    __syncthreads();
    if (wid == 0) {
        int t = wsum[lane];
        #pragma unroll
        for (int off = 1; off < 32; off <<= 1) {
            int u = __shfl_up_sync(0xffffffffu, t, off);
            if (lane >= off) t += u;
        }
        wsum[lane] = t;
    }
    __syncthreads();
    int run = (wid ? wsum[wid - 1] : 0) + s - sum;   // exclusive prefix of this chunk
    for (int i = start; i < end; i++) {
        int d = g_deg[i];
        g_off[i] = run;
        g_cur[i] = run;
        run += d;
    }
    if (tid == T - 1) g_off[N_NODES] = E;
}

__global__ __launch_bounds__(256)
void scatter_kernel(const void* __restrict__ eptr, int E) {
    int i = blockIdx.x * blockDim.x + threadIdx.x;
    if (i >= E) return;
    int src, dst;
    if (g_idx64) {
        const long long* e = (const long long*)eptr;
        src = (int)e[i];
        dst = (int)e[(size_t)E + i];
    } else {
        const int* e = (const int*)eptr;
        src = e[i];
        dst = e[E + i];
    }
    int pos = atomicAdd(&g_cur[dst], 1);
    g_src_sorted[pos] = src;
}

// ---------------- FFMA2 register-tiled fused GEMM + attention scores ----------------
// W transposed ([col][k]) with XOR-chunk swizzle in SMEM -> packed dual-fp32 FMAs
// pair along k with zero packing MOVs. Each thread: 4 nodes x 4 cols.
// HALF_OUT writes h as fp16 (uint2 per 4 cols); scores always fp32.
template<int F_OUT, int NT, bool HALF_OUT>
__global__ __launch_bounds__(512)
void gemm_scores_kernel(const float* __restrict__ x,
                        const float* __restrict__ WT,   // [F_OUT][F_IN] transposed
                        const float* __restrict__ a_src,
                        const float* __restrict__ a_dst,
                        void* __restrict__ h,
                        float* __restrict__ s_src,
                        float* __restrict__ s_dst) {
    constexpr int CG   = F_OUT / 4;      // col-groups (32 for F1, 16 for F2)
    constexpr int NG   = 512 / CG;       // node-groups (16 / 32)
    static_assert(NT == NG * 4, "tile mismatch");
    constexpr int D    = F_OUT / HEADS;  // per-head dim (16 / 8)
    constexpr int CGH  = D / 4;          // col-groups per head (4 / 2)
    constexpr int XROW = F_IN + 4;       // padded xs row

    extern __shared__ float sm[];
    float* Ws  = sm;                     // F_OUT * F_IN (swizzled, col-major rows)
    float* xs  = Ws + F_OUT * F_IN;      // NT * XROW
    float* as_ = xs + NT * XROW;         // F_OUT
    float* ad_ = as_ + F_OUT;            // F_OUT

    const int tid  = threadIdx.x;
    const int base = blockIdx.x * NT;

    for (int i = tid; i < F_OUT * (F_IN / 4); i += 512) {
        int r = i >> 5, q = i & 31;
        *(float4*)(Ws + r * F_IN + (((q) ^ ((r >> 2) & 7)) << 2)) =
            ((const float4*)WT)[i];
    }
    if (tid < F_OUT) { as_[tid] = a_src[tid]; ad_[tid] = a_dst[tid]; }

    for (int i = tid; i < NT * (F_IN / 4); i += 512) {
        int nl = i >> 5, cq = i & 31;
        int n  = base + nl;
        float4 v = (n < N_NODES) ? ((const float4*)x)[(size_t)n * (F_IN / 4) + cq]
                                 : make_float4(0.f, 0.f, 0.f, 0.f);
        *(float4*)(xs + nl * XROW + cq * 4) = v;
    }
    __syncthreads();

    const int cg = tid % CG;
    const int ng = tid / CG;
    const int colbase = cg * 4;
    const int swz = (cg & 7) << 2;
    const float* xbase = xs + ng * 4 * XROW;
    const float* wr0 = Ws + (colbase + 0) * F_IN;
    const float* wr1 = Ws + (colbase + 1) * F_IN;
    const float* wr2 = Ws + (colbase + 2) * F_IN;
    const float* wr3 = Ws + (colbase + 3) * F_IN;

    unsigned long long acc[4][4] = {};

    #pragma unroll 2
    for (int k4 = 0; k4 < F_IN / 4; ++k4) {
        ulonglong2 xp[4];
        #pragma unroll
        for (int m = 0; m < 4; ++m)
            xp[m] = *(const ulonglong2*)(xbase + m * XROW + k4 * 4);

        const int ko = (k4 * 4) ^ swz;
        ulonglong2 w0 = *(const ulonglong2*)(wr0 + ko);
        ulonglong2 w1 = *(const ulonglong2*)(wr1 + ko);
        ulonglong2 w2 = *(const ulonglong2*)(wr2 + ko);
        ulonglong2 w3 = *(const ulonglong2*)(wr3 + ko);

        #pragma unroll
        for (int m = 0; m < 4; ++m) {
            fma2(acc[m][0], xp[m].x, w0.x); fma2(acc[m][0], xp[m].y, w0.y);
            fma2(acc[m][1], xp[m].x, w1.x); fma2(acc[m][1], xp[m].y, w1.y);
            fma2(acc[m][2], xp[m].x, w2.x); fma2(acc[m][2], xp[m].y, w2.y);
            fma2(acc[m][3], xp[m].x, w3.x); fma2(acc[m][3], xp[m].y, w3.y);
        }
    }

    const float a0 = as_[colbase], a1 = as_[colbase + 1],
                a2 = as_[colbase + 2], a3 = as_[colbase + 3];
    const float d0 = ad_[colbase], d1 = ad_[colbase + 1],
                d2 = ad_[colbase + 2], d3 = ad_[colbase + 3];

    #pragma unroll
    for (int m = 0; m < 4; ++m) {
        float c0 = pair_sum(acc[m][0]);
        float c1 = pair_sum(acc[m][1]);
        float c2 = pair_sum(acc[m][2]);
        float c3 = pair_sum(acc[m][3]);
        float vs = c0 * a0 + c1 * a1 + c2 * a2 + c3 * a3;
        float vd = c0 * d0 + c1 * d1 + c2 * d2 + c3 * d3;
        #pragma unroll
        for (int off = 1; off < CGH; off <<= 1) {
            vs += __shfl_xor_sync(0xffffffffu, vs, off);
            vd += __shfl_xor_sync(0xffffffffu, vd, off);
        }
        int node = base + ng * 4 + m;
        if (node < N_NODES) {
            if (HALF_OUT) {
                union { __half2 h2[2]; uint2 u; } cv;
                cv.h2[0] = __floats2half2_rn(c0, c1);
                cv.h2[1] = __floats2half2_rn(c2, c3);
                *(uint2*)((__half*)h + (size_t)node * F_OUT + colbase) = cv.u;
            } else {
                *(float4*)((float*)h + (size_t)node * F_OUT + colbase) =
                    make_float4(c0, c1, c2, c3);
            }
            if ((cg & (CGH - 1)) == 0) {
                int head = cg / CGH;
                s_src[(size_t)node * HEADS + head] = vs;
                s_dst[(size_t)node * HEADS + head] = vd;
            }
        }
    }
}

// ---------------- gather aggregation: one (F_OUT/4)-lane group per dst ----------------
// Self-loop seeded analytically; edges walked from the dst-sorted CSR with 4-wide
// batched loads for MLP; row written once, coalesced, normalized + bias (+relu).
template<int F_OUT, bool RELU, bool HALF_IN>
__global__ __launch_bounds__(256)
void aggregate_kernel(const void* __restrict__ h,
                      const float* __restrict__ s_src,
                      const float* __restrict__ s_dst,
                      const float* __restrict__ b,
                      float* __restrict__ out) {
    constexpr int LPD = F_OUT / 4;        // lanes per dst (32 / 16)
    constexpr int D   = F_OUT / HEADS;
    int gt  = blockIdx.x * 256 + threadIdx.x;
    int dst = gt / LPD;
    if (dst >= N_NODES) return;
    int sub  = gt % LPD;
    int head = (sub * 4) / D;

    float sd = s_dst[(size_t)dst * HEADS + head];

    // self-loop
    float ex = __expf(lrelu(s_src[(size_t)dst * HEADS + head] + sd));
    float4 hv = load_h4<HALF_IN>(h, (size_t)dst, F_OUT, sub);
    float ax = ex * hv.x, ay = ex * hv.y, az = ex * hv.z, aw = ex * hv.w;
    float den = ex;

    int i = g_off[dst], end = g_off[dst + 1];
    for (; i + 4 <= end; i += 4) {
        int s0 = g_src_sorted[i];
        int s1 = g_src_sorted[i + 1];
        int s2 = g_src_sorted[i + 2];
        int s3 = g_src_sorted[i + 3];
        float z0 = s_src[(size_t)s0 * HEADS + head];
        float z1 = s_src[(size_t)s1 * HEADS + head];
        float z2 = s_src[(size_t)s2 * HEADS + head];
        float z3 = s_src[(size_t)s3 * HEADS + head];
        float4 v0 = load_h4<HALF_IN>(h, (size_t)s0, F_OUT, sub);
        float4 v1 = load_h4<HALF_IN>(h, (size_t)s1, F_OUT, sub);
        float4 v2 = load_h4<HALF_IN>(h, (size_t)s2, F_OUT, sub);
        float4 v3 = load_h4<HALF_IN>(h, (size_t)s3, F_OUT, sub);
        float e0 = __expf(lrelu(z0 + sd));
        float e1 = __expf(lrelu(z1 + sd));
        float e2 = __expf(lrelu(z2 + sd));
        float e3 = __expf(lrelu(z3 + sd));
        ax = fmaf(e0, v0.x, ax); ay = fmaf(e0, v0.y, ay);
        az = fmaf(e0, v0.z, az); aw = fmaf(e0, v0.w, aw);
        ax = fmaf(e1, v1.x, ax); ay = fmaf(e1, v1.y, ay);
        az = fmaf(e1, v1.z, az); aw = fmaf(e1, v1.w, aw);
        ax = fmaf(e2, v2.x, ax); ay = fmaf(e2, v2.y, ay);
        az = fmaf(e2, v2.z, az); aw = fmaf(e2, v2.w, aw);
        ax = fmaf(e3, v3.x, ax); ay = fmaf(e3, v3.y, ay);
        az = fmaf(e3, v3.z, az); aw = fmaf(e3, v3.w, aw);
        den += (e0 + e1) + (e2 + e3);
    }
    for (; i < end; ++i) {
        int s0 = g_src_sorted[i];
        float e0 = __expf(lrelu(s_src[(size_t)s0 * HEADS + head] + sd));
        float4 v0 = load_h4<HALF_IN>(h, (size_t)s0, F_OUT, sub);
        ax = fmaf(e0, v0.x, ax); ay = fmaf(e0, v0.y, ay);
        az = fmaf(e0, v0.z, az); aw = fmaf(e0, v0.w, aw);
        den += e0;
    }

    float inv = 1.f / (den + 1e-16f);
    float4 bb = ((const float4*)b)[sub];
    float4 o;
    o.x = fmaf(ax, inv, bb.x);
    o.y = fmaf(ay, inv, bb.y);
    o.z = fmaf(az, inv, bb.z);
    o.w = fmaf(aw, inv, bb.w);
    if (RELU) {
        o.x = fmaxf(o.x, 0.f); o.y = fmaxf(o.y, 0.f);
        o.z = fmaxf(o.z, 0.f); o.w = fmaxf(o.w, 0.f);
    }
    *(float4*)(out + (size_t)dst * F_OUT + sub * 4) = o;
}

// ---------------- host launcher ----------------
extern "C" void kernel_launch(void* const* d_in, const int* in_sizes, int n_in,
                              void* d_out, int out_size) {
    const float* x     = (const float*)d_in[0];
    const void*  edges = d_in[1];
    const float* W1    = (const float*)d_in[2];
    const float* a1s   = (const float*)d_in[3];
    const float* a1d   = (const float*)d_in[4];
    const float* b1    = (const float*)d_in[5];
    const float* W2    = (const float*)d_in[6];
    const float* a2s   = (const float*)d_in[7];
    const float* a2d   = (const float*)d_in[8];
    const float* b2    = (const float*)d_in[9];
    float* outp = (float*)d_out;

    const int E = in_sizes[1] / 2;

    float *h1, *o1, *ss1, *sd1, *h2, *ss2, *sd2, *wt1, *wt2;
    int* degp;
    cudaGetSymbolAddress((void**)&h1,  g_h1);
    cudaGetSymbolAddress((void**)&o1,  g_out1);
    cudaGetSymbolAddress((void**)&ss1, g_s_src1);
    cudaGetSymbolAddress((void**)&sd1, g_s_dst1);
    cudaGetSymbolAddress((void**)&h2,  g_h2);
    cudaGetSymbolAddress((void**)&ss2, g_s_src2);
    cudaGetSymbolAddress((void**)&sd2, g_s_dst2);
    cudaGetSymbolAddress((void**)&wt1, g_WT1);
    cudaGetSymbolAddress((void**)&wt2, g_WT2);
    cudaGetSymbolAddress((void**)&degp, g_deg);

    constexpr int NT1 = 64, NT2 = 128;
    constexpr int XROW = F_IN + 4;
    const int smem1 = (F_IN * F1 + NT1 * XROW + 2 * F1) * (int)sizeof(float);
    const int smem2 = (F_IN * F2 + NT2 * XROW + 2 * F2) * (int)sizeof(float);
    cudaFuncSetAttribute((const void*)gemm_scores_kernel<F1, NT1, true>,
                         cudaFuncAttributeMaxDynamicSharedMemorySize, smem1);
    cudaFuncSetAttribute((const void*)gemm_scores_kernel<F2, NT2, false>,
                         cudaFuncAttributeMaxDynamicSharedMemorySize, smem2);

    const int eblocks = (E + 255) / 256;

    // 0) dtype detect + weight transpose (merged) + CSR build
    prep_kernel<<<1 + (F_IN * F1 + F_IN * F2 + 255) / 256, 256>>>(
        (const long long*)edges, W1, W2);
    cudaMemsetAsync(degp, 0, N_NODES * sizeof(int));
    hist_kernel<<<eblocks, 256>>>(edges, E);
    scan_all_kernel<<<1, 1024>>>(E);
    scatter_kernel<<<eblocks, 256>>>(edges, E);

    // 1) layer 1: GEMM + scores (FFMA2), h1 in fp16
    gemm_scores_kernel<F1, NT1, true><<<(N_NODES + NT1 - 1) / NT1, 512, smem1>>>(
        x, wt1, a1s, a1d, (void*)h1, ss1, sd1);

    // 2) layer 1: gather-aggregate (fp16 h reads, +normalize +bias +relu fused)
    aggregate_kernel<F1, true, true><<<(N_NODES * (F1 / 4) + 255) / 256, 256>>>(
        (const void*)h1, ss1, sd1, b1, o1);

    // 3) layer 2: GEMM + scores (FFMA2), h2 fp32
    gemm_scores_kernel<F2, NT2, false><<<(N_NODES + NT2 - 1) / NT2, 512, smem2>>>(
        o1, wt2, a2s, a2d, (void*)h2, ss2, sd2);

    // 4) layer 2: gather-aggregate (+normalize +bias) -> final output
    aggregate_kernel<F2, false, false><<<(N_NODES * (F2 / 4) + 255) / 256, 256>>>(
        (const void*)h2, ss2, sd2, b2, outp);
}